// round 15
// baseline (speedup 1.0000x reference)
#include <cuda_runtime.h>
#include <cuda_fp16.h>

#define NN 50000
#define NP 800000   // undirected pairs
#define NE 1600000  // directed edges

// ---------------- scratch (static device globals; no allocations) ----------------
__device__ float  g_x1[NN * 64];
__device__ float  g_x2[NN * 64];
__device__ int    g_cnt[NN];
__device__ int    g_offs[NN + 1];
__device__ int    g_cur[NN];
__device__ int    g_srcs[NE];
__device__ __half g_PA[NN * 256];     // fp16 projection table A (conv1/conv2/ec2)
__device__ __half g_PB[NN * 256];     // fp16 projection table B (ec1)
__device__ float  g_o1[NP * 4];       // per-pair PB-side output contribution
__device__ float  g_Wc[16384];        // ec1: W1 @ Wl[0:128]
__device__ float  g_c0[128];          // ec1: b1 @ Wl[0:128] + bl
__device__ float  g_Wc2[384];         // ec2: 0.5 * W1e2 @ Wl2[0:3]
__device__ float  g_c2[4];            // ec2: b1e2 @ Wl2[0:3] + bl2
__device__ float  g_Wcc[384];         // 0.5 * Wc @ WlB   (fe1 folded into ec2)
__device__ float  g_wa3[4];           // wl128 @ WlB
__device__ float  g_wg3[4];           // wl129 @ WlB
__device__ float  g_cc[4];            // c0 @ WlB + c2
__device__ double g_loss[2];

__device__ __forceinline__ float lrelu(float z) { return z > 0.f ? z : 0.01f * z; }

// fp16 MMA m16n8k16
__device__ __forceinline__ void mma_f16(float c[4],
    unsigned a0, unsigned a1, unsigned a2, unsigned a3,
    unsigned b0, unsigned b1)
{
    asm volatile(
        "mma.sync.aligned.m16n8k16.row.col.f32.f16.f16.f32 "
        "{%0,%1,%2,%3}, {%4,%5,%6,%7}, {%8,%9}, {%0,%1,%2,%3};"
        : "+f"(c[0]), "+f"(c[1]), "+f"(c[2]), "+f"(c[3])
        : "r"(a0), "r"(a1), "r"(a2), "r"(a3), "r"(b0), "r"(b1));
}

// ---------------- packed f32x2 helpers ----------------
__device__ __forceinline__ unsigned long long pack2(float x)
{
    unsigned long long r;
    asm("mov.b64 %0, {%1, %1};" : "=l"(r) : "f"(x));
    return r;
}
__device__ __forceinline__ unsigned long long ffma2(
    unsigned long long a, unsigned long long b, unsigned long long c)
{
    unsigned long long d;
    asm("fma.rn.f32x2 %0, %1, %2, %3;" : "=l"(d) : "l"(a), "l"(b), "l"(c));
    return d;
}
__device__ __forceinline__ void unpack2(unsigned long long v, float& lo, float& hi)
{
    asm("mov.b64 {%0, %1}, %2;" : "=f"(lo), "=f"(hi) : "l"(v));
}

// half4 (uint2) -> 4 floats
__device__ __forceinline__ void h4_to_f4(uint2 u, float& f0, float& f1, float& f2, float& f3)
{
    __half2 p01 = *(__half2*)&u.x;
    __half2 p23 = *(__half2*)&u.y;
    float2 a = __half22float2(p01);
    float2 b = __half22float2(p23);
    f0 = a.x; f1 = a.y; f2 = b.x; f3 = b.y;
}

// ------------------------------------------------------------------
// Fused weight-precompute
__global__ void __launch_bounds__(384) fuseAB_kernel(
    const float* __restrict__ W1, const float* __restrict__ Wl,
    const float* __restrict__ b1, const float* __restrict__ bl,
    const float* __restrict__ W1e2, const float* __restrict__ Wl2,
    const float* __restrict__ b1e2, const float* __restrict__ bl2,
    float* __restrict__ Wc, float* __restrict__ c0,
    float* __restrict__ Wc2, float* __restrict__ c2)
{
    const int b = blockIdx.x, t = threadIdx.x;
    if (b < 43) {
        int id = b * 384 + t;
        if (id < 16384) {
            int r = id >> 7, c = id & 127;
            float s = 0.f;
#pragma unroll 8
            for (int k = 0; k < 128; k++) s += W1[r * 128 + k] * Wl[k * 128 + c];
            Wc[id] = s;
        }
    } else {
        if (t < 128) {
            float s = bl[t];
#pragma unroll 8
            for (int k = 0; k < 128; k++) s += b1[k] * Wl[k * 128 + t];
            c0[t] = s;
        }
        {
            int k = t / 3, c = t % 3;
            Wc2[t] = 0.5f * (W1e2[k * 3 + 0] * Wl2[0 + c] +
                             W1e2[k * 3 + 1] * Wl2[3 + c] +
                             W1e2[k * 3 + 2] * Wl2[6 + c]);
        }
        if (t < 3)
            c2[t] = b1e2[0] * Wl2[0 + t] + b1e2[1] * Wl2[3 + t] +
                    b1e2[2] * Wl2[6 + t] + bl2[t];
    }
}
__global__ void fuseC_kernel(const float* __restrict__ Wc, const float* __restrict__ c0,
                             const float* __restrict__ Wl1, const float* __restrict__ Wl2,
                             const float* __restrict__ c2,
                             float* __restrict__ Wcc, float* __restrict__ wa3,
                             float* __restrict__ wg3, float* __restrict__ cc)
{
    int id = threadIdx.x;   // 384
    int k = id / 3, c = id % 3;
    float s = 0.f;
#pragma unroll 8
    for (int j = 0; j < 128; j++) s += Wc[k * 128 + j] * Wl2[(3 + j) * 3 + c];
    Wcc[id] = 0.5f * s;
    if (id < 3) {
        float sa = 0.f, sg = 0.f, sc = 0.f;
        for (int j = 0; j < 128; j++) {
            float wb = Wl2[(3 + j) * 3 + id];
            sa += Wl1[128 * 128 + j] * wb;
            sg += Wl1[129 * 128 + j] * wb;
            sc += c0[j] * wb;
        }
        wa3[id] = sa; wg3[id] = sg; cc[id] = sc + c2[id];
    }
}

// ------------------------------------------------------------------
// CSR build
__global__ void count_kernel(const int* __restrict__ ei, int* __restrict__ cnt)
{
    int e = blockIdx.x * blockDim.x + threadIdx.x;
    if (e < NE) atomicAdd(&cnt[ei[NE + e]], 1);
}

__global__ void __launch_bounds__(1024) scan_kernel(const int* __restrict__ cnt,
                                                    int* __restrict__ offs)
{
    __shared__ int part[1024];
    const int t = threadIdx.x;
    const int CH = (NN + 1023) / 1024;
    const int base = t * CH;
    int s = 0;
    for (int j = 0; j < CH; j++) {
        int n = base + j;
        if (n < NN) s += cnt[n];
    }
    part[t] = s;
    __syncthreads();
    for (int off = 1; off < 1024; off <<= 1) {
        int v = (t >= off) ? part[t - off] : 0;
        __syncthreads();
        part[t] += v;
        __syncthreads();
    }
    int run = part[t] - s;
    for (int j = 0; j < CH; j++) {
        int n = base + j;
        if (n < NN) { offs[n] = run; run += cnt[n]; }
    }
    if (t == 1023) offs[NN] = part[1023];
}

__global__ void fill_kernel(const int* __restrict__ ei, const int* __restrict__ offs,
                            int* __restrict__ cur, int* __restrict__ srcs)
{
    int e = blockIdx.x * blockDim.x + threadIdx.x;
    if (e < NE) {
        int src = ei[e];
        int dst = ei[NE + e];
        int pos = atomicAdd(&cur[dst], 1);
        srcs[offs[dst] + pos] = src;
    }
}

// ------------------------------------------------------------------
// node_proj
__global__ void __launch_bounds__(256) node_proj_kernel(
    const float* __restrict__ x, const float* __restrict__ W0, __half* __restrict__ Ph)
{
    __shared__ float XT[64 * 68];
    __shared__ float WC[16 * 256];
    const int tid = threadIdx.x;
    const int nbase = blockIdx.x * 64;
#pragma unroll
    for (int i = 0; i < 4; i++) {
        int lin = tid * 4 + i;
        int r = lin >> 4, q = lin & 15;
        int node = nbase + r; if (node >= NN) node = NN - 1;
        float4 v = __ldg((const float4*)x + (size_t)node * 16 + q);
        XT[(q * 4 + 0) * 68 + r] = v.x;
        XT[(q * 4 + 1) * 68 + r] = v.y;
        XT[(q * 4 + 2) * 68 + r] = v.z;
        XT[(q * 4 + 3) * 68 + r] = v.w;
    }
    unsigned long long acc2[8][4];
#pragma unroll
    for (int i = 0; i < 8; i++)
#pragma unroll
        for (int j = 0; j < 4; j++) acc2[i][j] = 0ull;
    const int tr = tid >> 5, tc = tid & 31;
    for (int kc = 0; kc < 64; kc += 16) {
        __syncthreads();
#pragma unroll
        for (int i = 0; i < 4; i++) {
            int lin = tid + i * 256;
            int kk = lin >> 6, j4 = lin & 63;
            int j = j4 * 4;
            const float* src = (j < 128) ? (W0 + (kc + kk) * 128 + j)
                                         : (W0 + (64 + kc + kk) * 128 + (j - 128));
            *(float4*)&WC[kk * 256 + j] = *(const float4*)src;
        }
        __syncthreads();
#pragma unroll
        for (int kk = 0; kk < 16; kk++) {
            float4 a0 = *(const float4*)&XT[(kc + kk) * 68 + tr * 8];
            float4 a1 = *(const float4*)&XT[(kc + kk) * 68 + tr * 8 + 4];
            ulonglong2 w01 = *(const ulonglong2*)&WC[kk * 256 + tc * 8];
            ulonglong2 w23 = *(const ulonglong2*)&WC[kk * 256 + tc * 8 + 4];
            float a[8] = {a0.x, a0.y, a0.z, a0.w, a1.x, a1.y, a1.z, a1.w};
#pragma unroll
            for (int i = 0; i < 8; i++) {
                unsigned long long ap = pack2(a[i]);
                acc2[i][0] = ffma2(ap, w01.x, acc2[i][0]);
                acc2[i][1] = ffma2(ap, w01.y, acc2[i][1]);
                acc2[i][2] = ffma2(ap, w23.x, acc2[i][2]);
                acc2[i][3] = ffma2(ap, w23.y, acc2[i][3]);
            }
        }
    }
#pragma unroll
    for (int i = 0; i < 8; i++) {
        int node = nbase + tr * 8 + i;
        if (node < NN) {
            float o[8];
#pragma unroll
            for (int j = 0; j < 4; j++) unpack2(acc2[i][j], o[2 * j], o[2 * j + 1]);
            __half2 h0 = __floats2half2_rn(o[0], o[1]);
            __half2 h1 = __floats2half2_rn(o[2], o[3]);
            __half2 h2 = __floats2half2_rn(o[4], o[5]);
            __half2 h3 = __floats2half2_rn(o[6], o[7]);
            uint4 v;
            v.x = *(unsigned*)&h0; v.y = *(unsigned*)&h1;
            v.z = *(unsigned*)&h2; v.w = *(unsigned*)&h3;
            *(uint4*)&Ph[(size_t)node * 256 + tc * 8] = v;
        }
    }
}

// ------------------------------------------------------------------
// Fused CSR aggregation + per-node GEMM
__global__ void __launch_bounds__(256) aggregate_gemm_kernel(
    const __half* __restrict__ P, const int* __restrict__ offs,
    const int* __restrict__ srcs, const float* __restrict__ b0,
    const float* __restrict__ W1, const float* __restrict__ b1,
    float* __restrict__ x)
{
    __shared__ float W1S[128 * 64];
    __shared__ float HSH[8 * 128];
    __shared__ float B0S[128];
    __shared__ float B1S[64];
    const int tid = threadIdx.x;
    const int wid = tid >> 5, lane = tid & 31;

#pragma unroll
    for (int i = 0; i < 8; i++)
        ((float4*)W1S)[tid + i * 256] = ((const float4*)W1)[tid + i * 256];
    if (tid < 32) ((float4*)B0S)[tid] = ((const float4*)b0)[tid];
    else if (tid < 48) ((float4*)B1S)[tid - 32] = ((const float4*)b1)[tid - 32];
    __syncthreads();

    const int n = blockIdx.x * 8 + wid;
    if (n >= NN) return;

    const uint2* P4 = (const uint2*)P;
    float pbx, pby, pbz, pbw;
    h4_to_f4(__ldg(P4 + (size_t)n * 64 + 32 + lane), pbx, pby, pbz, pbw);
    float4 b0v = *(const float4*)&B0S[lane * 4];
    pbx += b0v.x; pby += b0v.y; pbz += b0v.z; pbw += b0v.w;

    const int beg = offs[n], end = offs[n + 1];
    float ax, ay, az, aw;
    float4 acc = make_float4(0.f, 0.f, 0.f, 0.f);
    int i = beg;
    for (; i + 8 <= end; i += 8) {
        uint2 u[8];
#pragma unroll
        for (int j = 0; j < 8; j++)
            u[j] = __ldg(P4 + (size_t)srcs[i + j] * 64 + lane);
#pragma unroll
        for (int j = 0; j < 8; j++) {
            h4_to_f4(u[j], ax, ay, az, aw);
            acc.x += lrelu(ax + pbx); acc.y += lrelu(ay + pby);
            acc.z += lrelu(az + pbz); acc.w += lrelu(aw + pbw);
        }
    }
    for (; i < end; i++) {
        int s = srcs[i];
        h4_to_f4(__ldg(P4 + (size_t)s * 64 + lane), ax, ay, az, aw);
        acc.x += lrelu(ax + pbx); acc.y += lrelu(ay + pby);
        acc.z += lrelu(az + pbz); acc.w += lrelu(aw + pbw);
    }
    *(float4*)&HSH[wid * 128 + lane * 4] = acc;
    __syncwarp();

    const float* h = &HSH[wid * 128];
    unsigned long long s2 = 0ull;
#pragma unroll 8
    for (int k = 0; k < 128; k++) {
        unsigned long long wv = *(const unsigned long long*)&W1S[k * 64 + lane * 2];
        s2 = ffma2(pack2(h[k]), wv, s2);
    }
    float s0f, s1f;
    unpack2(s2, s0f, s1f);
    int deg = end - beg;
    float inv = 1.f / fmaxf((float)deg, 1.f);
    float bf = deg > 0 ? 1.f : 0.f;
    float2 bv = *(const float2*)&B1S[lane * 2];
    *(float2*)&x[(size_t)n * 64 + lane * 2] =
        make_float2(s0f * inv + bv.x * bf, s1f * inv + bv.y * bf);
}

// ------------------------------------------------------------------
// EB kernel (PB-only work): per tile of 64 pairs
//   build HS1/HD1 from PB; loss1 HMMA; o1 = hs1@Wcc + act*wa3 + ang*wg3 + cc
#define EB_W1T  0        // half[128][136] = 8704 floats
#define EB_HD1  8704     // half[64][132] = 4224 floats
#define EB_HS1  12928    // float[64][132] = 8448
#define EB_WCC  21376    // 512 (128 x 4)
#define EB_B0B  21888    // 128
#define EB_WA3  22016
#define EB_WG3  22020
#define EB_CCV  22024    // 8
#define EB_SPI  22032    // 64
#define EB_DPI  22096    // 64
#define EB_RED  22160    // 16
#define EB_TOT  22176
#define EB_GRID 296
#define EB_NTILE 12500

__global__ void __launch_bounds__(512, 2) eb_kernel(
    const __half* __restrict__ PB, const int* __restrict__ ei,
    const float* __restrict__ act, const float* __restrict__ ang,
    const float* __restrict__ b0B, const float* __restrict__ W1,
    const float* __restrict__ Wcc,
    const float* __restrict__ wa3, const float* __restrict__ wg3,
    const float* __restrict__ ccv,
    float* __restrict__ o1buf, double* __restrict__ lossp)
{
    extern __shared__ float sm[];
    __half* W1T = (__half*)(sm + EB_W1T);
    __half* HD1h = (__half*)(sm + EB_HD1);
    float* HS1 = sm + EB_HS1;
    float* WCC = sm + EB_WCC;
    float* B0B = sm + EB_B0B;
    float* WA3 = sm + EB_WA3;
    float* WG3 = sm + EB_WG3;
    float* CCV = sm + EB_CCV;
    int* SP = (int*)(sm + EB_SPI);
    int* DP = (int*)(sm + EB_DPI);
    float* RED = sm + EB_RED;
    const int tid = threadIdx.x;

    for (int i = tid; i < 16384; i += 512) {
        int k = i >> 7, n = i & 127;
        W1T[n * 136 + k] = __float2half_rn(W1[i]);
    }
    for (int i = tid; i < 384; i += 512) {
        int k = i / 3, c = i % 3;
        WCC[k * 4 + c] = Wcc[i];
    }
    if (tid < 32) ((float4*)B0B)[tid] = ((const float4*)b0B)[tid];
    if (tid < 3) { WA3[tid] = wa3[tid]; WG3[tid] = wg3[tid]; CCV[tid] = ccv[tid]; }

    const int w = tid >> 5, lane = tid & 31;
    const int gid = lane >> 2, tig = lane & 3;
    const int m0 = (w & 3) * 16, n0 = (w >> 2) * 32;
    const int p = tid >> 3, q = tid & 7;
    float lsum1 = 0.f;

    for (int tile = blockIdx.x; tile < EB_NTILE; tile += EB_GRID) {
        const int pbase = tile * 64;
        __syncthreads();
        if (tid < 64) {
            SP[tid] = ei[pbase + tid];
            DP[tid] = ei[NP + pbase + tid];
        }
        __syncthreads();

        // build HS1 (fp32) / HD1 (fp16) from fp16 PB
#pragma unroll
        for (int it = 0; it < 4; it++) {
            int idx = tid + it * 512;
            int r = idx >> 5, c4 = idx & 31;
            int s = SP[r], d = DP[r];
            const uint2* Ps = (const uint2*)(PB + (size_t)s * 256);
            const uint2* Pd = (const uint2*)(PB + (size_t)d * 256);
            float a1x, a1y, a1z, a1w, b1x, b1y, b1z, b1w;
            float a2x, a2y, a2z, a2w, b2x, b2y, b2z, b2w;
            h4_to_f4(__ldg(Ps + c4),      a1x, a1y, a1z, a1w);
            h4_to_f4(__ldg(Pd + 32 + c4), b1x, b1y, b1z, b1w);
            h4_to_f4(__ldg(Pd + c4),      a2x, a2y, a2z, a2w);
            h4_to_f4(__ldg(Ps + 32 + c4), b2x, b2y, b2z, b2w);
            float4 b0v = *(const float4*)&B0B[c4 * 4];
            float h1, h2;
            float4 hs;
            float hdx, hdy, hdz, hdw;
            h1 = lrelu(a1x + b1x + b0v.x); h2 = lrelu(a2x + b2x + b0v.x);
            hs.x = h1 + h2; hdx = h1 - h2;
            h1 = lrelu(a1y + b1y + b0v.y); h2 = lrelu(a2y + b2y + b0v.y);
            hs.y = h1 + h2; hdy = h1 - h2;
            h1 = lrelu(a1z + b1z + b0v.z); h2 = lrelu(a2z + b2z + b0v.z);
            hs.z = h1 + h2; hdz = h1 - h2;
            h1 = lrelu(a1w + b1w + b0v.w); h2 = lrelu(a2w + b2w + b0v.w);
            hs.w = h1 + h2; hdw = h1 - h2;
            *(float4*)&HS1[r * 132 + c4 * 4] = hs;
            __half2 dlo = __floats2half2_rn(hdx, hdy);
            __half2 dhi = __floats2half2_rn(hdz, hdw);
            uint2 du; du.x = *(unsigned*)&dlo; du.y = *(unsigned*)&dhi;
            *(uint2*)&HD1h[r * 132 + c4 * 4] = du;
        }
        __syncthreads();

        // Phase A': o1 = hs1 @ Wcc  (8 threads/pair, 16 channels each)
        {
            const int gp = pbase + p;
            float o0 = 0.f, o1 = 0.f, o2 = 0.f;
#pragma unroll 4
            for (int j = 0; j < 16; j++) {
                int k = q * 16 + j;
                float f = HS1[p * 132 + k];
                const float* wv = &WCC[k * 4];
                o0 += f * wv[0];
                o1 += f * wv[1];
                o2 += f * wv[2];
            }
#pragma unroll
            for (int off = 4; off > 0; off >>= 1) {
                o0 += __shfl_down_sync(0xffffffffu, o0, off, 8);
                o1 += __shfl_down_sync(0xffffffffu, o1, off, 8);
                o2 += __shfl_down_sync(0xffffffffu, o2, off, 8);
            }
            if (q == 0) {
                float av = __ldg(act + gp), gv = __ldg(ang + gp);
                *(float4*)&o1buf[(size_t)gp * 4] = make_float4(
                    o0 + av * WA3[0] + gv * WG3[0] + CCV[0],
                    o1 + av * WA3[1] + gv * WG3[1] + CCV[1],
                    o2 + av * WA3[2] + gv * WG3[2] + CCV[2], 0.f);
            }
        }

        // Phase B: loss1 HMMA, all 16 warps
        {
            float c[4][4];
#pragma unroll
            for (int nt = 0; nt < 4; nt++)
#pragma unroll
                for (int j = 0; j < 4; j++) c[nt][j] = 0.f;
#pragma unroll 2
            for (int ks = 0; ks < 8; ks++) {
                int kb = ks * 16;
                unsigned a0 = *(const unsigned*)&HD1h[(m0 + gid) * 132 + kb + 2 * tig];
                unsigned a1 = *(const unsigned*)&HD1h[(m0 + 8 + gid) * 132 + kb + 2 * tig];
                unsigned a2 = *(const unsigned*)&HD1h[(m0 + gid) * 132 + kb + 8 + 2 * tig];
                unsigned a3 = *(const unsigned*)&HD1h[(m0 + 8 + gid) * 132 + kb + 8 + 2 * tig];
#pragma unroll
                for (int nt = 0; nt < 4; nt++) {
                    int n = n0 + nt * 8 + gid;
                    unsigned b0f = *(const unsigned*)&W1T[n * 136 + kb + 2 * tig];
                    unsigned b1f = *(const unsigned*)&W1T[n * 136 + kb + 8 + 2 * tig];
                    mma_f16(c[nt], a0, a1, a2, a3, b0f, b1f);
                }
            }
#pragma unroll
            for (int nt = 0; nt < 4; nt++)
#pragma unroll
                for (int j = 0; j < 4; j++) lsum1 += c[nt][j] * c[nt][j];
        }
    }

#pragma unroll
    for (int o = 16; o > 0; o >>= 1) lsum1 += __shfl_down_sync(0xffffffffu, lsum1, o);
    __syncthreads();
    if (lane == 0) RED[w] = lsum1;
    __syncthreads();
    if (tid == 0) {
        float l1 = 0.f;
#pragma unroll
        for (int ww = 0; ww < 16; ww++) l1 += RED[ww];
        atomicAdd(&lossp[0], (double)l1);
    }
}

// ------------------------------------------------------------------
// EA kernel (PA2 work): per pair, out = o1 + hs2@Wc2 ; loss2 += ||hd2@W1e2||^2
#define EA_GRID 592
#define EA_NTILE 25000

__global__ void __launch_bounds__(256) ea_kernel(
    const __half* __restrict__ PA2, const int* __restrict__ ei,
    const float* __restrict__ Wc2, const float* __restrict__ W1e2,
    const float* __restrict__ b0A, const float* __restrict__ o1buf,
    float* __restrict__ out, double* __restrict__ lossp)
{
    __shared__ float W6S[128 * 8];   // cols 0-2: Wc2, cols 4-6: W1e2
    __shared__ float B0A[128];
    __shared__ float RED[8];
    const int tid = threadIdx.x;

    for (int i = tid; i < 1024; i += 256) {
        int k = i >> 3, c = i & 7;
        float v = 0.f;
        if (c < 3) v = Wc2[k * 3 + c];
        else if (c >= 4 && c < 7) v = W1e2[k * 3 + (c - 4)];
        W6S[i] = v;
    }
    if (tid < 32) ((float4*)B0A)[tid] = ((const float4*)b0A)[tid];
    __syncthreads();

    const int pl = tid >> 3, q = tid & 7;   // 32 pairs/block, 8 threads/pair
    float lsum2 = 0.f;

    for (int tile = blockIdx.x; tile < EA_NTILE; tile += EA_GRID) {
        const int gp = tile * 32 + pl;
        int sv = 0, dv = 0;
        if (q == 0) { sv = ei[gp]; dv = ei[NP + gp]; }
        int s = __shfl_sync(0xffffffffu, sv, 0, 8);
        int d = __shfl_sync(0xffffffffu, dv, 0, 8);
        const uint2* Ps = (const uint2*)(PA2 + (size_t)s * 256);
        const uint2* Pd = (const uint2*)(PA2 + (size_t)d * 256);
        float o0 = 0.f, o1 = 0.f, o2 = 0.f, t0 = 0.f, t1 = 0.f, t2 = 0.f;
#pragma unroll
        for (int c8 = 0; c8 < 4; c8++) {
            int c4 = q * 4 + c8;
            float av1[4], bv1[4], av2[4], bv2[4];
            h4_to_f4(__ldg(Ps + c4),      av1[0], av1[1], av1[2], av1[3]);
            h4_to_f4(__ldg(Pd + 32 + c4), bv1[0], bv1[1], bv1[2], bv1[3]);
            h4_to_f4(__ldg(Pd + c4),      av2[0], av2[1], av2[2], av2[3]);
            h4_to_f4(__ldg(Ps + 32 + c4), bv2[0], bv2[1], bv2[2], bv2[3]);
            float4 b0v = *(const float4*)&B0A[c4 * 4];
            float b0a[4] = {b0v.x, b0v.y, b0v.z, b0v.w};
#pragma unroll
            for (int j = 0; j < 4; j++) {
                int k = c4 * 4 + j;
                float h1 = lrelu(av1[j] + bv1[j] + b0a[j]);
                float h2 = lrelu(av2[j] + bv2[j] + b0a[j]);
                float hs = h1 + h2, hd = h1 - h2;
                const float* wv = &W6S[k * 8];
                o0 += hs * wv[0];
                o1 += hs * wv[1];
                o2 += hs * wv[2];
                t0 += hd * wv[4];
                t1 += hd * wv[5];
                t2 += hd * wv[6];
            }
        }
#pragma unroll
        for (int off = 4; off > 0; off >>= 1) {
            o0 += __shfl_down_sync(0xffffffffu, o0, off, 8);
            o1 += __shfl_down_sync(0xffffffffu, o1, off, 8);
            o2 += __shfl_down_sync(0xffffffffu, o2, off, 8);
            t0 += __shfl_down_sync(0xffffffffu, t0, off, 8);
            t1 += __shfl_down_sync(0xffffffffu, t1, off, 8);
            t2 += __shfl_down_sync(0xffffffffu, t2, off, 8);
        }
        if (q == 0) {
            float4 ov = *(const float4*)&o1buf[(size_t)gp * 4];
            out[(size_t)gp * 3 + 0] = o0 + ov.x;
            out[(size_t)gp * 3 + 1] = o1 + ov.y;
            out[(size_t)gp * 3 + 2] = o2 + ov.z;
            lsum2 += t0 * t0 + t1 * t1 + t2 * t2;
        }
    }

#pragma unroll
    for (int o = 16; o > 0; o >>= 1) lsum2 += __shfl_down_sync(0xffffffffu, lsum2, o);
    __syncthreads();
    if ((tid & 31) == 0) RED[tid >> 5] = lsum2;
    __syncthreads();
    if (tid == 0) {
        float l2 = 0.f;
#pragma unroll
        for (int ww = 0; ww < 8; ww++) l2 += RED[ww];
        atomicAdd(&lossp[1], (double)l2);
    }
}

// ------------------------------------------------------------------
__global__ void finalize_kernel(float* __restrict__ out, int idx)
{
    double l = 0.5 * (g_loss[0] / (800000.0 * 128.0) + g_loss[1] / (800000.0 * 3.0));
    out[idx] = (float)l;
}

// ------------------------------------------------------------------
extern "C" void kernel_launch(void* const* d_in, const int* in_sizes, int n_in,
                              void* d_out, int out_size)
{
    (void)in_sizes; (void)n_in;
    const float* xnf  = (const float*)d_in[0];
    const int*   ei   = (const int*)d_in[1];
    const float* ang  = (const float*)d_in[2];
    const float* act  = (const float*)d_in[3];
    const float* nc1W0 = (const float*)d_in[5];
    const float* nc1b0 = (const float*)d_in[6];
    const float* nc1W1 = (const float*)d_in[7];
    const float* nc1b1 = (const float*)d_in[8];
    const float* ec1W0 = (const float*)d_in[9];
    const float* ec1b0 = (const float*)d_in[10];
    const float* ec1W1 = (const float*)d_in[11];
    const float* ec1b1 = (const float*)d_in[12];
    const float* ec1Wl = (const float*)d_in[13];
    const float* ec1bl = (const float*)d_in[14];
    const float* nc2W0 = (const float*)d_in[15];
    const float* nc2b0 = (const float*)d_in[16];
    const float* nc2W1 = (const float*)d_in[17];
    const float* nc2b1 = (const float*)d_in[18];
    const float* ec2W0 = (const float*)d_in[19];
    const float* ec2b0 = (const float*)d_in[20];
    const float* ec2W1 = (const float*)d_in[21];
    const float* ec2b1 = (const float*)d_in[22];
    const float* ec2Wl = (const float*)d_in[23];
    const float* ec2bl = (const float*)d_in[24];
    float* out = (float*)d_out;

    float *x1, *x2, *o1b, *Wc, *c0, *Wc2, *c2, *Wcc, *wa3, *wg3, *cc;
    __half *PA, *PB;
    int *cnt, *offs, *cur, *srcs;
    double* loss;
    cudaGetSymbolAddress((void**)&x1,   g_x1);
    cudaGetSymbolAddress((void**)&x2,   g_x2);
    cudaGetSymbolAddress((void**)&PA,   g_PA);
    cudaGetSymbolAddress((void**)&PB,   g_PB);
    cudaGetSymbolAddress((void**)&o1b,  g_o1);
    cudaGetSymbolAddress((void**)&Wc,   g_Wc);
    cudaGetSymbolAddress((void**)&c0,   g_c0);
    cudaGetSymbolAddress((void**)&Wc2,  g_Wc2);
    cudaGetSymbolAddress((void**)&c2,   g_c2);
    cudaGetSymbolAddress((void**)&Wcc,  g_Wcc);
    cudaGetSymbolAddress((void**)&wa3,  g_wa3);
    cudaGetSymbolAddress((void**)&wg3,  g_wg3);
    cudaGetSymbolAddress((void**)&cc,   g_cc);
    cudaGetSymbolAddress((void**)&cnt,  g_cnt);
    cudaGetSymbolAddress((void**)&offs, g_offs);
    cudaGetSymbolAddress((void**)&cur,  g_cur);
    cudaGetSymbolAddress((void**)&srcs, g_srcs);
    cudaGetSymbolAddress((void**)&loss, g_loss);

    // One-time init OUTSIDE graph capture.
    static int init_done = 0;
    static cudaStream_t s1, s2;
    static cudaEvent_t evFork, evCSR, evFuse, evX1, evEB;
    if (!init_done) {
        cudaFuncSetAttribute(eb_kernel,
                             cudaFuncAttributeMaxDynamicSharedMemorySize,
                             EB_TOT * sizeof(float));
        cudaStreamCreateWithFlags(&s1, cudaStreamNonBlocking);
        cudaStreamCreateWithFlags(&s2, cudaStreamNonBlocking);
        cudaEventCreateWithFlags(&evFork, cudaEventDisableTiming);
        cudaEventCreateWithFlags(&evCSR,  cudaEventDisableTiming);
        cudaEventCreateWithFlags(&evFuse, cudaEventDisableTiming);
        cudaEventCreateWithFlags(&evX1,   cudaEventDisableTiming);
        cudaEventCreateWithFlags(&evEB,   cudaEventDisableTiming);
        init_done = 1;
    }

    const int NB64 = (NN + 63) / 64;
    const int NAGG = (NN + 7) / 8;
    const cudaStream_t s0 = 0;

    cudaEventRecord(evFork, s0);
    cudaStreamWaitEvent(s1, evFork, 0);
    cudaStreamWaitEvent(s2, evFork, 0);

    // ---- s1: CSR build ----
    cudaMemsetAsync(cnt, 0, (size_t)NN * sizeof(int), s1);
    cudaMemsetAsync(cur, 0, (size_t)NN * sizeof(int), s1);
    count_kernel<<<(NE + 255) / 256, 256, 0, s1>>>(ei, cnt);
    scan_kernel<<<1, 1024, 0, s1>>>(cnt, offs);
    fill_kernel<<<(NE + 255) / 256, 256, 0, s1>>>(ei, offs, cur, srcs);
    cudaEventRecord(evCSR, s1);

    // ---- s2: weight fusions ----
    fuseAB_kernel<<<44, 384, 0, s2>>>(ec1W1, ec1Wl, ec1b1, ec1bl,
                                      ec2W1, ec2Wl, ec2b1, ec2bl,
                                      Wc, c0, Wc2, c2);
    fuseC_kernel<<<1, 384, 0, s2>>>(Wc, c0, ec1Wl, ec2Wl, c2, Wcc, wa3, wg3, cc);
    cudaEventRecord(evFuse, s2);

    // ---- s0: critical path ----
    cudaMemsetAsync(loss, 0, 2 * sizeof(double), s0);
    node_proj_kernel<<<NB64, 256, 0, s0>>>(xnf, nc1W0, PA);
    cudaStreamWaitEvent(s0, evCSR, 0);
    aggregate_gemm_kernel<<<NAGG, 256, 0, s0>>>(PA, offs, srcs, nc1b0, nc1W1, nc1b1, x1);
    cudaEventRecord(evX1, s0);

    // ---- s1: projE1 + EB (PB-only edge work), overlapped with conv2 chain ----
    cudaStreamWaitEvent(s1, evX1, 0);
    node_proj_kernel<<<NB64, 256, 0, s1>>>(x1, ec1W0, PB);
    cudaStreamWaitEvent(s1, evFuse, 0);
    eb_kernel<<<EB_GRID, 512, EB_TOT * sizeof(float), s1>>>(
        PB, ei, act, ang, ec1b0, ec1W1, Wcc, wa3, wg3, cc, o1b, loss);
    cudaEventRecord(evEB, s1);

    // ---- s0: conv layer 2 chain ----
    node_proj_kernel<<<NB64, 256, 0, s0>>>(x1, nc2W0, PA);
    aggregate_gemm_kernel<<<NAGG, 256, 0, s0>>>(PA, offs, srcs, nc2b0, nc2W1, nc2b1, x2);
    node_proj_kernel<<<NB64, 256, 0, s0>>>(x2, ec2W0, PA);

    // ---- s0: EA (PA2 edge work) after EB completes ----
    cudaStreamWaitEvent(s0, evEB, 0);
    ea_kernel<<<EA_GRID, 256, 0, s0>>>(PA, ei, Wc2, ec2W1, ec2b0, o1b, out, loss);

    finalize_kernel<<<1, 1, 0, s0>>>(out, out_size - 1);
}

// round 16
// speedup vs baseline: 1.7925x; 1.7925x over previous
#include <cuda_runtime.h>
#include <cuda_fp16.h>

#define NN 50000
#define NP 800000   // undirected pairs
#define NE 1600000  // directed edges

// ---------------- scratch (static device globals; no allocations) ----------------
__device__ float  g_x1[NN * 64];
__device__ float  g_x2[NN * 64];
__device__ int    g_cnt[NN];
__device__ int    g_offs[NN + 1];
__device__ int    g_cur[NN];
__device__ int    g_srcs[NE];
__device__ __half g_PA[NN * 256];     // fp16 projection table A (conv1/conv2/ec2)
__device__ __half g_PB[NN * 256];     // fp16 projection table B (ec1)
__device__ float  g_Wc[16384];        // ec1: W1 @ Wl[0:128]
__device__ float  g_c0[128];          // ec1: b1 @ Wl[0:128] + bl
__device__ float  g_Wc2[384];         // ec2: 0.5 * W1e2 @ Wl2[0:3]
__device__ float  g_c2[4];            // ec2: b1e2 @ Wl2[0:3] + bl2
__device__ float  g_Wcc[384];         // 0.5 * Wc @ WlB   (fe1 folded into ec2)
__device__ float  g_wa3[4];           // wl128 @ WlB
__device__ float  g_wg3[4];           // wl129 @ WlB
__device__ float  g_cc[4];            // c0 @ WlB + c2
__device__ double g_loss[2];

__device__ __forceinline__ float lrelu(float z) { return z > 0.f ? z : 0.01f * z; }

// fp16 MMA m16n8k16
__device__ __forceinline__ void mma_f16(float c[4],
    unsigned a0, unsigned a1, unsigned a2, unsigned a3,
    unsigned b0, unsigned b1)
{
    asm volatile(
        "mma.sync.aligned.m16n8k16.row.col.f32.f16.f16.f32 "
        "{%0,%1,%2,%3}, {%4,%5,%6,%7}, {%8,%9}, {%0,%1,%2,%3};"
        : "+f"(c[0]), "+f"(c[1]), "+f"(c[2]), "+f"(c[3])
        : "r"(a0), "r"(a1), "r"(a2), "r"(a3), "r"(b0), "r"(b1));
}

// ---------------- packed f32x2 helpers ----------------
__device__ __forceinline__ unsigned long long pack2(float x)
{
    unsigned long long r;
    asm("mov.b64 %0, {%1, %1};" : "=l"(r) : "f"(x));
    return r;
}
__device__ __forceinline__ unsigned long long ffma2(
    unsigned long long a, unsigned long long b, unsigned long long c)
{
    unsigned long long d;
    asm("fma.rn.f32x2 %0, %1, %2, %3;" : "=l"(d) : "l"(a), "l"(b), "l"(c));
    return d;
}
__device__ __forceinline__ void unpack2(unsigned long long v, float& lo, float& hi)
{
    asm("mov.b64 {%0, %1}, %2;" : "=f"(lo), "=f"(hi) : "l"(v));
}

// half4 (uint2) -> 4 floats
__device__ __forceinline__ void h4_to_f4(uint2 u, float& f0, float& f1, float& f2, float& f3)
{
    __half2 p01 = *(__half2*)&u.x;
    __half2 p23 = *(__half2*)&u.y;
    float2 a = __half22float2(p01);
    float2 b = __half22float2(p23);
    f0 = a.x; f1 = a.y; f2 = b.x; f3 = b.y;
}

// ------------------------------------------------------------------
// Fused weight-precompute
__global__ void __launch_bounds__(384) fuseAB_kernel(
    const float* __restrict__ W1, const float* __restrict__ Wl,
    const float* __restrict__ b1, const float* __restrict__ bl,
    const float* __restrict__ W1e2, const float* __restrict__ Wl2,
    const float* __restrict__ b1e2, const float* __restrict__ bl2,
    float* __restrict__ Wc, float* __restrict__ c0,
    float* __restrict__ Wc2, float* __restrict__ c2)
{
    const int b = blockIdx.x, t = threadIdx.x;
    if (b < 43) {
        int id = b * 384 + t;
        if (id < 16384) {
            int r = id >> 7, c = id & 127;
            float s = 0.f;
#pragma unroll 8
            for (int k = 0; k < 128; k++) s += W1[r * 128 + k] * Wl[k * 128 + c];
            Wc[id] = s;
        }
    } else {
        if (t < 128) {
            float s = bl[t];
#pragma unroll 8
            for (int k = 0; k < 128; k++) s += b1[k] * Wl[k * 128 + t];
            c0[t] = s;
        }
        {
            int k = t / 3, c = t % 3;
            Wc2[t] = 0.5f * (W1e2[k * 3 + 0] * Wl2[0 + c] +
                             W1e2[k * 3 + 1] * Wl2[3 + c] +
                             W1e2[k * 3 + 2] * Wl2[6 + c]);
        }
        if (t < 3)
            c2[t] = b1e2[0] * Wl2[0 + t] + b1e2[1] * Wl2[3 + t] +
                    b1e2[2] * Wl2[6 + t] + bl2[t];
    }
}
__global__ void fuseC_kernel(const float* __restrict__ Wc, const float* __restrict__ c0,
                             const float* __restrict__ Wl1, const float* __restrict__ Wl2,
                             const float* __restrict__ c2,
                             float* __restrict__ Wcc, float* __restrict__ wa3,
                             float* __restrict__ wg3, float* __restrict__ cc)
{
    int id = threadIdx.x;   // 384
    int k = id / 3, c = id % 3;
    float s = 0.f;
#pragma unroll 8
    for (int j = 0; j < 128; j++) s += Wc[k * 128 + j] * Wl2[(3 + j) * 3 + c];
    Wcc[id] = 0.5f * s;
    if (id < 3) {
        float sa = 0.f, sg = 0.f, sc = 0.f;
        for (int j = 0; j < 128; j++) {
            float wb = Wl2[(3 + j) * 3 + id];
            sa += Wl1[128 * 128 + j] * wb;
            sg += Wl1[129 * 128 + j] * wb;
            sc += c0[j] * wb;
        }
        wa3[id] = sa; wg3[id] = sg; cc[id] = sc + c2[id];
    }
}

// ------------------------------------------------------------------
// CSR build
__global__ void count_kernel(const int* __restrict__ ei, int* __restrict__ cnt)
{
    int e = blockIdx.x * blockDim.x + threadIdx.x;
    if (e < NE) atomicAdd(&cnt[ei[NE + e]], 1);
}

__global__ void __launch_bounds__(1024) scan_kernel(const int* __restrict__ cnt,
                                                    int* __restrict__ offs)
{
    __shared__ int part[1024];
    const int t = threadIdx.x;
    const int CH = (NN + 1023) / 1024;
    const int base = t * CH;
    int s = 0;
    for (int j = 0; j < CH; j++) {
        int n = base + j;
        if (n < NN) s += cnt[n];
    }
    part[t] = s;
    __syncthreads();
    for (int off = 1; off < 1024; off <<= 1) {
        int v = (t >= off) ? part[t - off] : 0;
        __syncthreads();
        part[t] += v;
        __syncthreads();
    }
    int run = part[t] - s;
    for (int j = 0; j < CH; j++) {
        int n = base + j;
        if (n < NN) { offs[n] = run; run += cnt[n]; }
    }
    if (t == 1023) offs[NN] = part[1023];
}

__global__ void fill_kernel(const int* __restrict__ ei, const int* __restrict__ offs,
                            int* __restrict__ cur, int* __restrict__ srcs)
{
    int e = blockIdx.x * blockDim.x + threadIdx.x;
    if (e < NE) {
        int src = ei[e];
        int dst = ei[NE + e];
        int pos = atomicAdd(&cur[dst], 1);
        srcs[offs[dst] + pos] = src;
    }
}

// ------------------------------------------------------------------
// node_proj
__global__ void __launch_bounds__(256) node_proj_kernel(
    const float* __restrict__ x, const float* __restrict__ W0, __half* __restrict__ Ph)
{
    __shared__ float XT[64 * 68];
    __shared__ float WC[16 * 256];
    const int tid = threadIdx.x;
    const int nbase = blockIdx.x * 64;
#pragma unroll
    for (int i = 0; i < 4; i++) {
        int lin = tid * 4 + i;
        int r = lin >> 4, q = lin & 15;
        int node = nbase + r; if (node >= NN) node = NN - 1;
        float4 v = __ldg((const float4*)x + (size_t)node * 16 + q);
        XT[(q * 4 + 0) * 68 + r] = v.x;
        XT[(q * 4 + 1) * 68 + r] = v.y;
        XT[(q * 4 + 2) * 68 + r] = v.z;
        XT[(q * 4 + 3) * 68 + r] = v.w;
    }
    unsigned long long acc2[8][4];
#pragma unroll
    for (int i = 0; i < 8; i++)
#pragma unroll
        for (int j = 0; j < 4; j++) acc2[i][j] = 0ull;
    const int tr = tid >> 5, tc = tid & 31;
    for (int kc = 0; kc < 64; kc += 16) {
        __syncthreads();
#pragma unroll
        for (int i = 0; i < 4; i++) {
            int lin = tid + i * 256;
            int kk = lin >> 6, j4 = lin & 63;
            int j = j4 * 4;
            const float* src = (j < 128) ? (W0 + (kc + kk) * 128 + j)
                                         : (W0 + (64 + kc + kk) * 128 + (j - 128));
            *(float4*)&WC[kk * 256 + j] = *(const float4*)src;
        }
        __syncthreads();
#pragma unroll
        for (int kk = 0; kk < 16; kk++) {
            float4 a0 = *(const float4*)&XT[(kc + kk) * 68 + tr * 8];
            float4 a1 = *(const float4*)&XT[(kc + kk) * 68 + tr * 8 + 4];
            ulonglong2 w01 = *(const ulonglong2*)&WC[kk * 256 + tc * 8];
            ulonglong2 w23 = *(const ulonglong2*)&WC[kk * 256 + tc * 8 + 4];
            float a[8] = {a0.x, a0.y, a0.z, a0.w, a1.x, a1.y, a1.z, a1.w};
#pragma unroll
            for (int i = 0; i < 8; i++) {
                unsigned long long ap = pack2(a[i]);
                acc2[i][0] = ffma2(ap, w01.x, acc2[i][0]);
                acc2[i][1] = ffma2(ap, w01.y, acc2[i][1]);
                acc2[i][2] = ffma2(ap, w23.x, acc2[i][2]);
                acc2[i][3] = ffma2(ap, w23.y, acc2[i][3]);
            }
        }
    }
#pragma unroll
    for (int i = 0; i < 8; i++) {
        int node = nbase + tr * 8 + i;
        if (node < NN) {
            float o[8];
#pragma unroll
            for (int j = 0; j < 4; j++) unpack2(acc2[i][j], o[2 * j], o[2 * j + 1]);
            __half2 h0 = __floats2half2_rn(o[0], o[1]);
            __half2 h1 = __floats2half2_rn(o[2], o[3]);
            __half2 h2 = __floats2half2_rn(o[4], o[5]);
            __half2 h3 = __floats2half2_rn(o[6], o[7]);
            uint4 v;
            v.x = *(unsigned*)&h0; v.y = *(unsigned*)&h1;
            v.z = *(unsigned*)&h2; v.w = *(unsigned*)&h3;
            *(uint4*)&Ph[(size_t)node * 256 + tc * 8] = v;
        }
    }
}

// ------------------------------------------------------------------
// Fused CSR aggregation + per-node GEMM — 16 nodes/block (512 threads),
// halves per-block W1 staging vs 8 nodes/block.
__global__ void __launch_bounds__(512) aggregate_gemm_kernel(
    const __half* __restrict__ P, const int* __restrict__ offs,
    const int* __restrict__ srcs, const float* __restrict__ b0,
    const float* __restrict__ W1, const float* __restrict__ b1,
    float* __restrict__ x)
{
    __shared__ float W1S[128 * 64];   // 32 KB
    __shared__ float HSH[16 * 128];   // 8 KB
    __shared__ float B0S[128];
    __shared__ float B1S[64];
    const int tid = threadIdx.x;
    const int wid = tid >> 5, lane = tid & 31;

#pragma unroll
    for (int i = 0; i < 4; i++)
        ((float4*)W1S)[tid + i * 512] = ((const float4*)W1)[tid + i * 512];
    if (tid < 32) ((float4*)B0S)[tid] = ((const float4*)b0)[tid];
    else if (tid < 48) ((float4*)B1S)[tid - 32] = ((const float4*)b1)[tid - 32];
    __syncthreads();

    const int n = blockIdx.x * 16 + wid;
    if (n >= NN) return;

    const uint2* P4 = (const uint2*)P;
    float pbx, pby, pbz, pbw;
    h4_to_f4(__ldg(P4 + (size_t)n * 64 + 32 + lane), pbx, pby, pbz, pbw);
    float4 b0v = *(const float4*)&B0S[lane * 4];
    pbx += b0v.x; pby += b0v.y; pbz += b0v.z; pbw += b0v.w;

    const int beg = offs[n], end = offs[n + 1];
    float ax, ay, az, aw;
    float4 acc = make_float4(0.f, 0.f, 0.f, 0.f);
    int i = beg;
    for (; i + 8 <= end; i += 8) {
        uint2 u[8];
#pragma unroll
        for (int j = 0; j < 8; j++)
            u[j] = __ldg(P4 + (size_t)srcs[i + j] * 64 + lane);
#pragma unroll
        for (int j = 0; j < 8; j++) {
            h4_to_f4(u[j], ax, ay, az, aw);
            acc.x += lrelu(ax + pbx); acc.y += lrelu(ay + pby);
            acc.z += lrelu(az + pbz); acc.w += lrelu(aw + pbw);
        }
    }
    for (; i < end; i++) {
        int s = srcs[i];
        h4_to_f4(__ldg(P4 + (size_t)s * 64 + lane), ax, ay, az, aw);
        acc.x += lrelu(ax + pbx); acc.y += lrelu(ay + pby);
        acc.z += lrelu(az + pbz); acc.w += lrelu(aw + pbw);
    }
    *(float4*)&HSH[wid * 128 + lane * 4] = acc;
    __syncwarp();

    const float* h = &HSH[wid * 128];
    unsigned long long s2 = 0ull;
#pragma unroll 8
    for (int k = 0; k < 128; k++) {
        unsigned long long wv = *(const unsigned long long*)&W1S[k * 64 + lane * 2];
        s2 = ffma2(pack2(h[k]), wv, s2);
    }
    float s0f, s1f;
    unpack2(s2, s0f, s1f);
    int deg = end - beg;
    float inv = 1.f / fmaxf((float)deg, 1.f);
    float bf = deg > 0 ? 1.f : 0.f;
    float2 bv = *(const float2*)&B1S[lane * 2];
    *(float2*)&x[(size_t)n * 64 + lane * 2] =
        make_float2(s0f * inv + bv.x * bf, s1f * inv + bv.y * bf);
}

// ------------------------------------------------------------------
// merged edge kernel — sequential phases: all threads matvec (8/pair), then
// all 16 warps HMMA. 2 blocks/SM. (R13 known-good)
#define EF_W1T  0        // half[128][136] transposed (W1T[n][k]) = 8704 floats
#define EF_HD1  8704     // half[64][132] = 4224 floats
#define EF_HS1  12928    // float[64][132] = 8448
#define EF_W12  21376    // 1568
#define EF_B0A  22944
#define EF_B0B  23072
#define EF_WA3  23200
#define EF_WG3  23208
#define EF_CCV  23216
#define EF_SPI  23232
#define EF_DPI  23296
#define EF_RED  23360    // 32
#define EF_TOT  23392
#define EF_GRID 296
#define EF_NTILE 12500
#define W12(k) ((k) * 12 + (((k) >> 5) << 2))

__global__ void __launch_bounds__(512, 2) edge_fused_kernel(
    const __half* __restrict__ PB, const __half* __restrict__ PA2,
    const int* __restrict__ ei,
    const float* __restrict__ act, const float* __restrict__ ang,
    const float* __restrict__ b0B, const float* __restrict__ b0A,
    const float* __restrict__ W1,
    const float* __restrict__ Wc2, const float* __restrict__ W1e2,
    const float* __restrict__ Wcc,
    const float* __restrict__ wa3, const float* __restrict__ wg3,
    const float* __restrict__ ccv,
    float* __restrict__ out, double* __restrict__ lossp)
{
    extern __shared__ float sm[];
    __half* W1T = (__half*)(sm + EF_W1T);   // [n][k] stride 136
    __half* HD1h = (__half*)(sm + EF_HD1);  // [r][k] stride 132
    float* HS1 = sm + EF_HS1;               // [r][c] stride 132
    float* W12S = sm + EF_W12;
    float* B0A = sm + EF_B0A;
    float* B0B = sm + EF_B0B;
    float* WA3 = sm + EF_WA3;
    float* WG3 = sm + EF_WG3;
    float* CCV = sm + EF_CCV;
    int* SP = (int*)(sm + EF_SPI);
    int* DP = (int*)(sm + EF_DPI);
    float* RED = sm + EF_RED;
    const int tid = threadIdx.x;

    for (int i = tid; i < 16384; i += 512) {
        int k = i >> 7, n = i & 127;
        W1T[n * 136 + k] = __float2half_rn(W1[i]);
    }
    for (int i = tid; i < 1152; i += 512) {
        int k = i / 9, c = i % 9;
        float v = (c < 3) ? Wc2[k * 3 + c]
                : (c < 6) ? W1e2[k * 3 + (c - 3)]
                          : Wcc[k * 3 + (c - 6)];
        W12S[W12(k) + c] = v;
    }
    if (tid < 32) ((float4*)B0A)[tid] = ((const float4*)b0A)[tid];
    else if (tid < 64) ((float4*)B0B)[tid - 32] = ((const float4*)b0B)[tid - 32];
    if (tid < 3) { WA3[tid] = wa3[tid]; WG3[tid] = wg3[tid]; CCV[tid] = ccv[tid]; }

    const int w = tid >> 5, lane = tid & 31;
    const int gid = lane >> 2, tig = lane & 3;
    const int m0 = (w & 3) * 16, n0 = (w >> 2) * 32;   // 16 warps cover 64x128
    const int p = tid >> 3, q = tid & 7;               // 8 threads per pair
    float lsum1 = 0.f, lsum2 = 0.f;

    for (int tile = blockIdx.x; tile < EF_NTILE; tile += EF_GRID) {
        const int pbase = tile * 64;
        __syncthreads();
        if (tid < 64) {
            SP[tid] = ei[pbase + tid];
            DP[tid] = ei[NP + pbase + tid];
        }
        __syncthreads();

        // build HS1 (fp32) / HD1 (fp16) from fp16 PB
#pragma unroll
        for (int it = 0; it < 4; it++) {
            int idx = tid + it * 512;
            int r = idx >> 5, c4 = idx & 31;
            int s = SP[r], d = DP[r];
            const uint2* Ps = (const uint2*)(PB + (size_t)s * 256);
            const uint2* Pd = (const uint2*)(PB + (size_t)d * 256);
            float a1x, a1y, a1z, a1w, b1x, b1y, b1z, b1w;
            float a2x, a2y, a2z, a2w, b2x, b2y, b2z, b2w;
            h4_to_f4(__ldg(Ps + c4),      a1x, a1y, a1z, a1w);
            h4_to_f4(__ldg(Pd + 32 + c4), b1x, b1y, b1z, b1w);
            h4_to_f4(__ldg(Pd + c4),      a2x, a2y, a2z, a2w);
            h4_to_f4(__ldg(Ps + 32 + c4), b2x, b2y, b2z, b2w);
            float4 b0v = *(const float4*)&B0B[c4 * 4];
            float h1, h2;
            float4 hs;
            float hdx, hdy, hdz, hdw;
            h1 = lrelu(a1x + b1x + b0v.x); h2 = lrelu(a2x + b2x + b0v.x);
            hs.x = h1 + h2; hdx = h1 - h2;
            h1 = lrelu(a1y + b1y + b0v.y); h2 = lrelu(a2y + b2y + b0v.y);
            hs.y = h1 + h2; hdy = h1 - h2;
            h1 = lrelu(a1z + b1z + b0v.z); h2 = lrelu(a2z + b2z + b0v.z);
            hs.z = h1 + h2; hdz = h1 - h2;
            h1 = lrelu(a1w + b1w + b0v.w); h2 = lrelu(a2w + b2w + b0v.w);
            hs.w = h1 + h2; hdw = h1 - h2;
            *(float4*)&HS1[r * 132 + c4 * 4] = hs;
            __half2 dlo = __floats2half2_rn(hdx, hdy);
            __half2 dhi = __floats2half2_rn(hdz, hdw);
            uint2 du; du.x = *(unsigned*)&dlo; du.y = *(unsigned*)&dhi;
            *(uint2*)&HD1h[r * 132 + c4 * 4] = du;
        }
        __syncthreads();

        // ---- Phase A: per-pair matvec, 8 threads/pair (fp16 PA2 gathers) ----
        {
            const int gp = pbase + p;
            const int s = SP[p], d = DP[p];
            const uint2* Ps = (const uint2*)(PA2 + (size_t)s * 256);
            const uint2* Pd = (const uint2*)(PA2 + (size_t)d * 256);
            float o0 = 0.f, o1 = 0.f, o2 = 0.f, t0 = 0.f, t1 = 0.f, t2 = 0.f;
#pragma unroll
            for (int c8 = 0; c8 < 4; c8++) {
                int c4 = q * 4 + c8;
                float av1[4], bv1[4], av2[4], bv2[4];
                h4_to_f4(__ldg(Ps + c4),      av1[0], av1[1], av1[2], av1[3]);
                h4_to_f4(__ldg(Pd + 32 + c4), bv1[0], bv1[1], bv1[2], bv1[3]);
                h4_to_f4(__ldg(Pd + c4),      av2[0], av2[1], av2[2], av2[3]);
                h4_to_f4(__ldg(Ps + 32 + c4), bv2[0], bv2[1], bv2[2], bv2[3]);
                float4 hv = *(const float4*)&HS1[p * 132 + c4 * 4];
                float4 b0v = *(const float4*)&B0A[c4 * 4];
                float hsv[4] = {hv.x, hv.y, hv.z, hv.w};
                float b0a[4] = {b0v.x, b0v.y, b0v.z, b0v.w};
#pragma unroll
                for (int j = 0; j < 4; j++) {
                    int k = c4 * 4 + j;
                    float h1 = lrelu(av1[j] + bv1[j] + b0a[j]);
                    float h2 = lrelu(av2[j] + bv2[j] + b0a[j]);
                    float hsx = h1 + h2, hd = h1 - h2, f = hsv[j];
                    const float* wv = &W12S[W12(k)];
                    o0 += hsx * wv[0] + f * wv[6];
                    o1 += hsx * wv[1] + f * wv[7];
                    o2 += hsx * wv[2] + f * wv[8];
                    t0 += hd * wv[3];
                    t1 += hd * wv[4];
                    t2 += hd * wv[5];
                }
            }
#pragma unroll
            for (int off = 4; off > 0; off >>= 1) {
                o0 += __shfl_down_sync(0xffffffffu, o0, off, 8);
                o1 += __shfl_down_sync(0xffffffffu, o1, off, 8);
                o2 += __shfl_down_sync(0xffffffffu, o2, off, 8);
                t0 += __shfl_down_sync(0xffffffffu, t0, off, 8);
                t1 += __shfl_down_sync(0xffffffffu, t1, off, 8);
                t2 += __shfl_down_sync(0xffffffffu, t2, off, 8);
            }
            if (q == 0) {
                float av = __ldg(act + gp), gv = __ldg(ang + gp);
                out[(size_t)gp * 3 + 0] = o0 + av * WA3[0] + gv * WG3[0] + CCV[0];
                out[(size_t)gp * 3 + 1] = o1 + av * WA3[1] + gv * WG3[1] + CCV[1];
                out[(size_t)gp * 3 + 2] = o2 + av * WA3[2] + gv * WG3[2] + CCV[2];
                lsum2 += t0 * t0 + t1 * t1 + t2 * t2;
            }
        }

        // ---- Phase B: loss1 HMMA, all 16 warps ----
        {
            float c[4][4];
#pragma unroll
            for (int nt = 0; nt < 4; nt++)
#pragma unroll
                for (int j = 0; j < 4; j++) c[nt][j] = 0.f;
#pragma unroll 2
            for (int ks = 0; ks < 8; ks++) {
                int kb = ks * 16;
                unsigned a0 = *(const unsigned*)&HD1h[(m0 + gid) * 132 + kb + 2 * tig];
                unsigned a1 = *(const unsigned*)&HD1h[(m0 + 8 + gid) * 132 + kb + 2 * tig];
                unsigned a2 = *(const unsigned*)&HD1h[(m0 + gid) * 132 + kb + 8 + 2 * tig];
                unsigned a3 = *(const unsigned*)&HD1h[(m0 + 8 + gid) * 132 + kb + 8 + 2 * tig];
#pragma unroll
                for (int nt = 0; nt < 4; nt++) {
                    int n = n0 + nt * 8 + gid;
                    unsigned b0f = *(const unsigned*)&W1T[n * 136 + kb + 2 * tig];
                    unsigned b1f = *(const unsigned*)&W1T[n * 136 + kb + 8 + 2 * tig];
                    mma_f16(c[nt], a0, a1, a2, a3, b0f, b1f);
                }
            }
#pragma unroll
            for (int nt = 0; nt < 4; nt++)
#pragma unroll
                for (int j = 0; j < 4; j++) lsum1 += c[nt][j] * c[nt][j];
        }
    }

    // final loss reduce (both buckets per warp)
#pragma unroll
    for (int o = 16; o > 0; o >>= 1) {
        lsum1 += __shfl_down_sync(0xffffffffu, lsum1, o);
        lsum2 += __shfl_down_sync(0xffffffffu, lsum2, o);
    }
    __syncthreads();
    if (lane == 0) { RED[w] = lsum1; RED[16 + w] = lsum2; }
    __syncthreads();
    if (tid == 0) {
        float l1 = 0.f, l2 = 0.f;
#pragma unroll
        for (int ww = 0; ww < 16; ww++) { l1 += RED[ww]; l2 += RED[16 + ww]; }
        atomicAdd(&lossp[0], (double)l1);
        atomicAdd(&lossp[1], (double)l2);
    }
}

// ------------------------------------------------------------------
__global__ void finalize_kernel(float* __restrict__ out, int idx)
{
    double l = 0.5 * (g_loss[0] / (800000.0 * 128.0) + g_loss[1] / (800000.0 * 3.0));
    out[idx] = (float)l;
}

// ------------------------------------------------------------------
extern "C" void kernel_launch(void* const* d_in, const int* in_sizes, int n_in,
                              void* d_out, int out_size)
{
    (void)in_sizes; (void)n_in;
    const float* xnf  = (const float*)d_in[0];
    const int*   ei   = (const int*)d_in[1];
    const float* ang  = (const float*)d_in[2];
    const float* act  = (const float*)d_in[3];
    const float* nc1W0 = (const float*)d_in[5];
    const float* nc1b0 = (const float*)d_in[6];
    const float* nc1W1 = (const float*)d_in[7];
    const float* nc1b1 = (const float*)d_in[8];
    const float* ec1W0 = (const float*)d_in[9];
    const float* ec1b0 = (const float*)d_in[10];
    const float* ec1W1 = (const float*)d_in[11];
    const float* ec1b1 = (const float*)d_in[12];
    const float* ec1Wl = (const float*)d_in[13];
    const float* ec1bl = (const float*)d_in[14];
    const float* nc2W0 = (const float*)d_in[15];
    const float* nc2b0 = (const float*)d_in[16];
    const float* nc2W1 = (const float*)d_in[17];
    const float* nc2b1 = (const float*)d_in[18];
    const float* ec2W0 = (const float*)d_in[19];
    const float* ec2b0 = (const float*)d_in[20];
    const float* ec2W1 = (const float*)d_in[21];
    const float* ec2b1 = (const float*)d_in[22];
    const float* ec2Wl = (const float*)d_in[23];
    const float* ec2bl = (const float*)d_in[24];
    float* out = (float*)d_out;

    float *x1, *x2, *Wc, *c0, *Wc2, *c2, *Wcc, *wa3, *wg3, *cc;
    __half *PA, *PB;
    int *cnt, *offs, *cur, *srcs;
    double* loss;
    cudaGetSymbolAddress((void**)&x1,   g_x1);
    cudaGetSymbolAddress((void**)&x2,   g_x2);
    cudaGetSymbolAddress((void**)&PA,   g_PA);
    cudaGetSymbolAddress((void**)&PB,   g_PB);
    cudaGetSymbolAddress((void**)&Wc,   g_Wc);
    cudaGetSymbolAddress((void**)&c0,   g_c0);
    cudaGetSymbolAddress((void**)&Wc2,  g_Wc2);
    cudaGetSymbolAddress((void**)&c2,   g_c2);
    cudaGetSymbolAddress((void**)&Wcc,  g_Wcc);
    cudaGetSymbolAddress((void**)&wa3,  g_wa3);
    cudaGetSymbolAddress((void**)&wg3,  g_wg3);
    cudaGetSymbolAddress((void**)&cc,   g_cc);
    cudaGetSymbolAddress((void**)&cnt,  g_cnt);
    cudaGetSymbolAddress((void**)&offs, g_offs);
    cudaGetSymbolAddress((void**)&cur,  g_cur);
    cudaGetSymbolAddress((void**)&srcs, g_srcs);
    cudaGetSymbolAddress((void**)&loss, g_loss);

    // One-time init OUTSIDE graph capture.
    static int init_done = 0;
    static cudaStream_t s1, s2;
    static cudaEvent_t evFork, evCSR, evFuse, evX1, evPB;
    if (!init_done) {
        cudaFuncSetAttribute(edge_fused_kernel,
                             cudaFuncAttributeMaxDynamicSharedMemorySize,
                             EF_TOT * sizeof(float));
        cudaStreamCreateWithFlags(&s1, cudaStreamNonBlocking);
        cudaStreamCreateWithFlags(&s2, cudaStreamNonBlocking);
        cudaEventCreateWithFlags(&evFork, cudaEventDisableTiming);
        cudaEventCreateWithFlags(&evCSR,  cudaEventDisableTiming);
        cudaEventCreateWithFlags(&evFuse, cudaEventDisableTiming);
        cudaEventCreateWithFlags(&evX1,   cudaEventDisableTiming);
        cudaEventCreateWithFlags(&evPB,   cudaEventDisableTiming);
        init_done = 1;
    }

    const int NB64 = (NN + 63) / 64;
    const int NAGG = (NN + 15) / 16;
    const cudaStream_t s0 = 0;

    cudaEventRecord(evFork, s0);
    cudaStreamWaitEvent(s1, evFork, 0);
    cudaStreamWaitEvent(s2, evFork, 0);

    // ---- s1: CSR build ----
    cudaMemsetAsync(cnt, 0, (size_t)NN * sizeof(int), s1);
    cudaMemsetAsync(cur, 0, (size_t)NN * sizeof(int), s1);
    count_kernel<<<(NE + 255) / 256, 256, 0, s1>>>(ei, cnt);
    scan_kernel<<<1, 1024, 0, s1>>>(cnt, offs);
    fill_kernel<<<(NE + 255) / 256, 256, 0, s1>>>(ei, offs, cur, srcs);
    cudaEventRecord(evCSR, s1);

    // ---- s2: weight fusions ----
    fuseAB_kernel<<<44, 384, 0, s2>>>(ec1W1, ec1Wl, ec1b1, ec1bl,
                                      ec2W1, ec2Wl, ec2b1, ec2bl,
                                      Wc, c0, Wc2, c2);
    fuseC_kernel<<<1, 384, 0, s2>>>(Wc, c0, ec1Wl, ec2Wl, c2, Wcc, wa3, wg3, cc);
    cudaEventRecord(evFuse, s2);

    // ---- s0: critical path ----
    cudaMemsetAsync(loss, 0, 2 * sizeof(double), s0);
    node_proj_kernel<<<NB64, 256, 0, s0>>>(xnf, nc1W0, PA);
    cudaStreamWaitEvent(s0, evCSR, 0);
    aggregate_gemm_kernel<<<NAGG, 512, 0, s0>>>(PA, offs, srcs, nc1b0, nc1W1, nc1b1, x1);
    cudaEventRecord(evX1, s0);

    // side: projection for edge conv 1 (needs x1 only)
    cudaStreamWaitEvent(s1, evX1, 0);
    node_proj_kernel<<<NB64, 256, 0, s1>>>(x1, ec1W0, PB);
    cudaEventRecord(evPB, s1);

    // main: conv layer 2 chain
    node_proj_kernel<<<NB64, 256, 0, s0>>>(x1, nc2W0, PA);
    aggregate_gemm_kernel<<<NAGG, 512, 0, s0>>>(PA, offs, srcs, nc2b0, nc2W1, nc2b1, x2);
    node_proj_kernel<<<NB64, 256, 0, s0>>>(x2, ec2W0, PA);

    // join and run merged edge convs
    cudaStreamWaitEvent(s0, evPB, 0);
    cudaStreamWaitEvent(s0, evFuse, 0);
    edge_fused_kernel<<<EF_GRID, 512, EF_TOT * sizeof(float), s0>>>(
        PB, PA, ei, act, ang, ec1b0, ec2b0, ec1W1,
        Wc2, ec2W1, Wcc, wa3, wg3, cc, out, loss);

    finalize_kernel<<<1, 1, 0, s0>>>(out, out_size - 1);
}